// round 4
// baseline (speedup 1.0000x reference)
#include <cuda_runtime.h>
#include <cuda_bf16.h>
#include <cstdint>

// Problem constants (fixed by the dataset)
#define NN 50000
#define EE 800000
#define DIN 128
#define HC 128      // H*C
#define CC 64       // per-head channels
#define HH 2
#define ED 32

typedef unsigned long long ULL;

// ---------------------------------------------------------------------------
// Scratch (allocation-free rule: one big __device__ array, sliced by offsets)
// Layout (floats):
//   q   : N*128
//   k   : N*128
//   v   : N*128
//   p   : N*64   (p[n][h*32+d] = sum_c q[n][h*64+c] * We[d][h*64+c])
//   num : N*128  (unnormalized softmax-weighted sum of v[src])
//   r   : N*64   (r[n][h*32+d] = sum_{edges->n} w_h * ea_d)
//   den : N*2
// ---------------------------------------------------------------------------
#define OFF_Q   ((size_t)0)
#define OFF_K   ((size_t)6400000)
#define OFF_V   ((size_t)12800000)
#define OFF_P   ((size_t)19200000)
#define OFF_NUM ((size_t)22400000)
#define OFF_R   ((size_t)28800000)
#define OFF_DEN ((size_t)32000000)
#define BUF_TOTAL ((size_t)32100000)
#define ZERO_COUNT ((size_t)(BUF_TOTAL - OFF_NUM))   // num + r + den contiguous

__device__ float g_buf[BUF_TOTAL];

// ---------------------------------------------------------------------------
// Packed fp32x2 helpers (Blackwell FFMA2 path — only reachable via PTX)
// ---------------------------------------------------------------------------
__device__ __forceinline__ void ffma2(ULL &d, ULL a, ULL b) {
    asm volatile("fma.rn.f32x2 %0, %1, %2, %3;" : "=l"(d) : "l"(a), "l"(b), "l"(d));
}
__device__ __forceinline__ ULL packdup(float x) {
    ULL r; asm("mov.b64 %0, {%1, %2};" : "=l"(r) : "f"(x), "f"(x)); return r;
}
__device__ __forceinline__ float2 unpack2(ULL v) {
    float2 r; asm("mov.b64 {%0, %1}, %2;" : "=f"(r.x), "=f"(r.y) : "l"(v)); return r;
}

// ---------------------------------------------------------------------------
// Kernel 1: fused node GEMMs.  out[gr][c] = sum_k x[gr][k]*W[k][c] + bias[c]
// blockIdx.y selects (Wq,bq,q) / (Wk,bk,k) / (Wv,bv,v) / (Wskip,bskip,d_out)
// 128x128 tile per block, 256 threads, 8x8 per thread via FFMA2 pairs.
// ---------------------------------------------------------------------------
#define ASTRIDE 130   // padded BM stride for the transposed A tile

__global__ __launch_bounds__(256, 2)
void gemm_qkvs(const float* __restrict__ x, int Nn,
               const float* __restrict__ Wq, const float* __restrict__ bq, float* __restrict__ oq,
               const float* __restrict__ Wk, const float* __restrict__ bk, float* __restrict__ ok,
               const float* __restrict__ Wv, const float* __restrict__ bv, float* __restrict__ ov,
               const float* __restrict__ Ws, const float* __restrict__ bs, float* __restrict__ os)
{
    __shared__ __align__(16) float As[32 * ASTRIDE];
    __shared__ __align__(16) float Bs[32 * 128];

    const float* W; const float* bias; float* out;
    int m = blockIdx.y;
    if (m == 0)      { W = Wq; bias = bq; out = oq; }
    else if (m == 1) { W = Wk; bias = bk; out = ok; }
    else if (m == 2) { W = Wv; bias = bv; out = ov; }
    else             { W = Ws; bias = bs; out = os; }

    int rowBase = blockIdx.x * 128;
    int tid = threadIdx.x;
    int tx = tid & 15;       // col-octet index
    int ty = tid >> 4;       // row-octet index

    ULL acc[4][8];
    #pragma unroll
    for (int i = 0; i < 4; i++)
        #pragma unroll
        for (int j = 0; j < 8; j++) acc[i][j] = 0ull;

    #pragma unroll
    for (int kt = 0; kt < 4; kt++) {
        int k0 = kt * 32;
        // --- load A tile (128 rows x 32 k), store transposed As[k][row]
        #pragma unroll
        for (int it = 0; it < 4; it++) {
            int fi  = tid + it * 256;     // 0..1023 float4 slots
            int row = fi >> 3;            // 0..127
            int c4  = fi & 7;             // 0..7
            int gr  = rowBase + row;
            float4 v = make_float4(0.f, 0.f, 0.f, 0.f);
            if (gr < Nn) v = *(const float4*)(x + (size_t)gr * DIN + k0 + c4 * 4);
            As[(c4 * 4 + 0) * ASTRIDE + row] = v.x;
            As[(c4 * 4 + 1) * ASTRIDE + row] = v.y;
            As[(c4 * 4 + 2) * ASTRIDE + row] = v.z;
            As[(c4 * 4 + 3) * ASTRIDE + row] = v.w;
        }
        // --- load B tile (32 k x 128 cols)
        #pragma unroll
        for (int it = 0; it < 4; it++) {
            int fi = tid + it * 256;
            int kk = fi >> 5;             // 0..31
            int c4 = fi & 31;             // 0..31
            *(float4*)(&Bs[kk * 128 + c4 * 4]) =
                *(const float4*)(W + (size_t)(k0 + kk) * HC + c4 * 4);
        }
        __syncthreads();

        #pragma unroll
        for (int k = 0; k < 32; k++) {
            const ULL* ap = (const ULL*)(&As[k * ASTRIDE + ty * 8]);
            ULL a0 = ap[0], a1 = ap[1], a2 = ap[2], a3 = ap[3];
            float4 b03 = *(const float4*)(&Bs[k * 128 + tx * 8]);
            float4 b47 = *(const float4*)(&Bs[k * 128 + tx * 8 + 4]);
            ULL bd[8];
            bd[0] = packdup(b03.x); bd[1] = packdup(b03.y);
            bd[2] = packdup(b03.z); bd[3] = packdup(b03.w);
            bd[4] = packdup(b47.x); bd[5] = packdup(b47.y);
            bd[6] = packdup(b47.z); bd[7] = packdup(b47.w);
            #pragma unroll
            for (int j = 0; j < 8; j++) {
                ffma2(acc[0][j], a0, bd[j]);
                ffma2(acc[1][j], a1, bd[j]);
                ffma2(acc[2][j], a2, bd[j]);
                ffma2(acc[3][j], a3, bd[j]);
            }
        }
        __syncthreads();
    }

    // --- epilogue: unpack, add bias, store
    #pragma unroll
    for (int j = 0; j < 8; j++) {
        int col = tx * 8 + j;
        float bv = __ldg(bias + col);
        #pragma unroll
        for (int i2 = 0; i2 < 4; i2++) {
            float2 v = unpack2(acc[i2][j]);
            int gr = rowBase + ty * 8 + i2 * 2;
            if (gr < Nn)     out[(size_t)gr * HC + col]       = v.x + bv;
            if (gr + 1 < Nn) out[(size_t)(gr + 1) * HC + col] = v.y + bv;
        }
    }
}

// ---------------------------------------------------------------------------
// Kernel 2: p[n][h*32+d] = sum_{c<64} q[n][h*64+c] * We[d][h*64+c]
// warp per node, lane = d. We in smem with stride 129 (conflict-free columns).
// ---------------------------------------------------------------------------
__global__ __launch_bounds__(256)
void p_kernel(const float* __restrict__ gq, const float* __restrict__ We,
              float* __restrict__ gp, int Nn)
{
    __shared__ float Ws[32 * 129];
    for (int i = threadIdx.x; i < ED * HC; i += blockDim.x)
        Ws[(i >> 7) * 129 + (i & 127)] = __ldg(&We[i]);
    __syncthreads();

    int warpId = (blockIdx.x * blockDim.x + threadIdx.x) >> 5;
    int lane   = threadIdx.x & 31;
    int nw     = (gridDim.x * blockDim.x) >> 5;

    for (int n = warpId; n < Nn; n += nw) {
        const float* qb = gq + (size_t)n * HC;
        const float* wrow = &Ws[lane * 129];     // We[d=lane][*]
        float acc0 = 0.f, acc1 = 0.f;
        #pragma unroll
        for (int c4 = 0; c4 < 16; c4++) {
            float4 qa = *(const float4*)(qb + c4 * 4);
            float4 qc = *(const float4*)(qb + 64 + c4 * 4);
            acc0 += qa.x * wrow[c4 * 4]     + qa.y * wrow[c4 * 4 + 1]
                  + qa.z * wrow[c4 * 4 + 2] + qa.w * wrow[c4 * 4 + 3];
            acc1 += qc.x * wrow[64 + c4 * 4]     + qc.y * wrow[64 + c4 * 4 + 1]
                  + qc.z * wrow[64 + c4 * 4 + 2] + qc.w * wrow[64 + c4 * 4 + 3];
        }
        gp[(size_t)n * 64 + lane]      = acc0;   // head 0, d = lane
        gp[(size_t)n * 64 + 32 + lane] = acc1;   // head 1, d = lane
    }
}

// ---------------------------------------------------------------------------
// Kernel 3: edge pass (single pass, no max-subtraction).
// warp per edge, lane handles channels {l, l+32} (head0) and {l+64, l+96}(head1).
//   alpha_h = (q[dst]·k[src] + ea·p[dst])_h / 8 ;  w = exp(alpha)
//   num[dst] += w_h * v[src];  r[dst][h*32+d] += w_h*ea_d;  den[dst][h] += w_h
// ---------------------------------------------------------------------------
__global__ __launch_bounds__(256)
void edge_kernel(const int* __restrict__ ei, const float* __restrict__ ea,
                 const float* __restrict__ gq, const float* __restrict__ gk,
                 const float* __restrict__ gv, const float* __restrict__ gp,
                 float* __restrict__ gnum, float* __restrict__ gr,
                 float* __restrict__ gden, int E)
{
    int warpId = (blockIdx.x * blockDim.x + threadIdx.x) >> 5;
    int lane   = threadIdx.x & 31;
    int nw     = (gridDim.x * blockDim.x) >> 5;

    for (int e = warpId; e < E; e += nw) {
        int src = __ldg(&ei[e]);
        int dst = __ldg(&ei[E + e]);
        float eav = __ldg(&ea[(size_t)e * ED + lane]);

        const float* qb = gq + (size_t)dst * HC;
        const float* kb = gk + (size_t)src * HC;
        const float* vb = gv + (size_t)src * HC;
        const float* pb = gp + (size_t)dst * 64;

        float q0 = __ldg(qb + lane),      q1 = __ldg(qb + 32 + lane);
        float q2 = __ldg(qb + 64 + lane), q3 = __ldg(qb + 96 + lane);
        float k0 = __ldg(kb + lane),      k1 = __ldg(kb + 32 + lane);
        float k2 = __ldg(kb + 64 + lane), k3 = __ldg(kb + 96 + lane);

        float s0 = q0 * k0 + q1 * k1 + eav * __ldg(pb + lane);        // head 0 partial
        float s1 = q2 * k2 + q3 * k3 + eav * __ldg(pb + 32 + lane);   // head 1 partial

        #pragma unroll
        for (int o = 16; o > 0; o >>= 1) {
            s0 += __shfl_xor_sync(0xffffffffu, s0, o);
            s1 += __shfl_xor_sync(0xffffffffu, s1, o);
        }
        float w0 = __expf(s0 * 0.125f);   // 1/sqrt(64)
        float w1 = __expf(s1 * 0.125f);

        if (lane == 0) atomicAdd(&gden[2 * dst],     w0);
        if (lane == 1) atomicAdd(&gden[2 * dst + 1], w1);

        float v0 = __ldg(vb + lane),      v1 = __ldg(vb + 32 + lane);
        float v2 = __ldg(vb + 64 + lane), v3 = __ldg(vb + 96 + lane);

        float* nb = gnum + (size_t)dst * HC;
        atomicAdd(nb + lane,      w0 * v0);
        atomicAdd(nb + 32 + lane, w0 * v1);
        atomicAdd(nb + 64 + lane, w1 * v2);
        atomicAdd(nb + 96 + lane, w1 * v3);

        float* rb = gr + (size_t)dst * 64;
        atomicAdd(rb + lane,      w0 * eav);   // head 0, d = lane
        atomicAdd(rb + 32 + lane, w1 * eav);   // head 1, d = lane
    }
}

// ---------------------------------------------------------------------------
// Kernel 4: finalize.
//   out[n][c] = (num[n][c] + sum_d r[n][h*32+d]*We[d][c]) / (den[n][h]+1e-16)
//               + skip (already resident in d_out)
// warp per node; lane handles channels {l, l+32, l+64, l+96}.
// ---------------------------------------------------------------------------
__global__ __launch_bounds__(256)
void finalize_kernel(const float* __restrict__ gnum, const float* __restrict__ gr,
                     const float* __restrict__ gden, const float* __restrict__ We,
                     float* __restrict__ out, int Nn)
{
    __shared__ float Ws[32 * 128];
    for (int i = threadIdx.x; i < ED * HC; i += blockDim.x)
        Ws[i] = __ldg(&We[i]);
    __syncthreads();

    int warpId = (blockIdx.x * blockDim.x + threadIdx.x) >> 5;
    int lane   = threadIdx.x & 31;
    int nw     = (gridDim.x * blockDim.x) >> 5;

    for (int n = warpId; n < Nn; n += nw) {
        float r0 = gr[(size_t)n * 64 + lane];        // head 0, d = lane
        float r1 = gr[(size_t)n * 64 + 32 + lane];   // head 1, d = lane
        float a0 = 0.f, a1 = 0.f, a2 = 0.f, a3 = 0.f;
        #pragma unroll
        for (int d = 0; d < 32; d++) {
            float rh0 = __shfl_sync(0xffffffffu, r0, d);
            float rh1 = __shfl_sync(0xffffffffu, r1, d);
            const float* wr = &Ws[d * 128];
            a0 += rh0 * wr[lane];
            a1 += rh0 * wr[32 + lane];
            a2 += rh1 * wr[64 + lane];
            a3 += rh1 * wr[96 + lane];
        }
        float inv0 = 1.0f / (gden[2 * n]     + 1e-16f);
        float inv1 = 1.0f / (gden[2 * n + 1] + 1e-16f);
        const float* nb = gnum + (size_t)n * HC;
        float* ob = out + (size_t)n * HC;
        ob[lane]      += (nb[lane]      + a0) * inv0;
        ob[32 + lane] += (nb[32 + lane] + a1) * inv0;
        ob[64 + lane] += (nb[64 + lane] + a2) * inv1;
        ob[96 + lane] += (nb[96 + lane] + a3) * inv1;
    }
}

// ---------------------------------------------------------------------------
// Launch
// inputs: 0 x, 1 edge_index, 2 edge_attr, 3 Wq, 4 bq, 5 Wk, 6 bk, 7 Wv, 8 bv,
//         9 We, 10 Wskip, 11 bskip ;  out: [N, 128] float32
// ---------------------------------------------------------------------------
extern "C" void kernel_launch(void* const* d_in, const int* in_sizes, int n_in,
                              void* d_out, int out_size)
{
    const float* x     = (const float*)d_in[0];
    const int*   ei    = (const int*)d_in[1];
    const float* ea    = (const float*)d_in[2];
    const float* Wq    = (const float*)d_in[3];
    const float* bq    = (const float*)d_in[4];
    const float* Wk    = (const float*)d_in[5];
    const float* bk    = (const float*)d_in[6];
    const float* Wv    = (const float*)d_in[7];
    const float* bv    = (const float*)d_in[8];
    const float* We    = (const float*)d_in[9];
    const float* Wsk   = (const float*)d_in[10];
    const float* bsk   = (const float*)d_in[11];
    float*       out   = (float*)d_out;

    int Nn = in_sizes[0] / DIN;
    int E  = in_sizes[1] / 2;

    float* base = nullptr;
    cudaGetSymbolAddress((void**)&base, g_buf);
    float* gq   = base + OFF_Q;
    float* gk   = base + OFF_K;
    float* gv   = base + OFF_V;
    float* gp   = base + OFF_P;
    float* gnum = base + OFF_NUM;
    float* gr   = base + OFF_R;
    float* gden = base + OFF_DEN;

    // zero accumulators (num + r + den are contiguous)
    cudaMemsetAsync(gnum, 0, ZERO_COUNT * sizeof(float), 0);

    // node GEMMs (skip goes straight into d_out)
    dim3 ggrid((Nn + 127) / 128, 4);
    gemm_qkvs<<<ggrid, 256>>>(x, Nn,
                              Wq, bq, gq,
                              Wk, bk, gk,
                              Wv, bv, gv,
                              Wsk, bsk, out);

    // p = q contracted with We (per head)
    p_kernel<<<1480, 256>>>(gq, We, gp, Nn);

    // single edge pass
    edge_kernel<<<2960, 256>>>(ei, ea, gq, gk, gv, gp, gnum, gr, gden, E);

    // finalize: normalize + r@We + skip
    finalize_kernel<<<1480, 256>>>(gnum, gr, gden, We, out, Nn);
}